// round 1
// baseline (speedup 1.0000x reference)
#include <cuda_runtime.h>
#include <math.h>

#define BB   32
#define CI   64
#define CO   64
#define HH   128
#define WWD  128
#define KK   4
#define HID  16

// scratch (no allocations allowed)
__device__ float g_gap[BB][CI];
__device__ float g_weff[BB][CO][CI][9];

// ---------------------------------------------------------------------------
// Kernel A: global average pool  g[b][c] = mean(x[b,c,:,:])
// grid (CI, BB), 256 threads
// ---------------------------------------------------------------------------
__global__ void gap_kernel(const float* __restrict__ x) {
    int c = blockIdx.x, b = blockIdx.y;
    const float4* p = (const float4*)(x + (((size_t)b * CI + c) << 14));
    float s = 0.f;
    #pragma unroll 4
    for (int i = threadIdx.x; i < 4096; i += 256) {
        float4 v = p[i];
        s += (v.x + v.y) + (v.z + v.w);
    }
    #pragma unroll
    for (int o = 16; o; o >>= 1) s += __shfl_xor_sync(0xffffffffu, s, o);
    __shared__ float ws[8];
    if ((threadIdx.x & 31) == 0) ws[threadIdx.x >> 5] = s;
    __syncthreads();
    if (threadIdx.x == 0) {
        float t = 0.f;
        #pragma unroll
        for (int i = 0; i < 8; i++) t += ws[i];
        g_gap[b][c] = t * (1.0f / 16384.0f);
    }
}

// ---------------------------------------------------------------------------
// Kernel B: attention branch + fused dynamic-weight combine
// grid (BB), 256 threads
// ---------------------------------------------------------------------------
__global__ void attn_weff_kernel(const float* __restrict__ weight,
                                 const float* __restrict__ mlp_w,
                                 const float* __restrict__ mlp_b,
                                 const float* __restrict__ wK, const float* __restrict__ bK,
                                 const float* __restrict__ wO, const float* __restrict__ bO,
                                 const float* __restrict__ wI, const float* __restrict__ bI,
                                 const float* __restrict__ wH, const float* __restrict__ bH,
                                 const float* __restrict__ wW, const float* __restrict__ bW) {
    int b   = blockIdx.x;
    int tid = threadIdx.x;

    __shared__ float sg[CI], sh[HID];
    __shared__ float saK[KK], saO[CO], saI[CI], saH[3], saW[3];

    if (tid < CI) sg[tid] = g_gap[b][tid];
    __syncthreads();

    if (tid < HID) {
        float s = mlp_b[tid];
        #pragma unroll
        for (int c = 0; c < CI; c++) s = fmaf(sg[c], mlp_w[tid * CI + c], s);
        sh[tid] = fmaxf(s, 0.f);
    }
    __syncthreads();

    if (tid < KK) {
        float s = bK[tid];
        #pragma unroll
        for (int j = 0; j < HID; j++) s = fmaf(sh[j], wK[tid * HID + j], s);
        saK[tid] = s;  // logits; softmax below
    } else if (tid >= 32 && tid < 32 + CO) {
        int o = tid - 32;
        float s = bO[o];
        #pragma unroll
        for (int j = 0; j < HID; j++) s = fmaf(sh[j], wO[o * HID + j], s);
        saO[o] = 1.f / (1.f + expf(-s));
    } else if (tid >= 96 && tid < 96 + CI) {
        int i = tid - 96;
        float s = bI[i];
        #pragma unroll
        for (int j = 0; j < HID; j++) s = fmaf(sh[j], wI[i * HID + j], s);
        saI[i] = 1.f / (1.f + expf(-s));
    } else if (tid >= 160 && tid < 163) {
        int h = tid - 160;
        float s = bH[h];
        #pragma unroll
        for (int j = 0; j < HID; j++) s = fmaf(sh[j], wH[h * HID + j], s);
        saH[h] = 1.f / (1.f + expf(-s));
    } else if (tid >= 164 && tid < 167) {
        int w = tid - 164;
        float s = bW[w];
        #pragma unroll
        for (int j = 0; j < HID; j++) s = fmaf(sh[j], wW[w * HID + j], s);
        saW[w] = 1.f / (1.f + expf(-s));
    }
    __syncthreads();

    if (tid == 0) {
        // softmax over K
        float m = fmaxf(fmaxf(saK[0], saK[1]), fmaxf(saK[2], saK[3]));
        float e0 = expf(saK[0] - m), e1 = expf(saK[1] - m),
              e2 = expf(saK[2] - m), e3 = expf(saK[3] - m);
        float inv = 1.f / (e0 + e1 + e2 + e3);
        saK[0] = e0 * inv; saK[1] = e1 * inv; saK[2] = e2 * inv; saK[3] = e3 * inv;
        // normalize aH, aW
        float hs = 1.f / (saH[0] + saH[1] + saH[2] + 1e-6f);
        saH[0] *= hs; saH[1] *= hs; saH[2] *= hs;
        float vs = 1.f / (saW[0] + saW[1] + saW[2] + 1e-6f);
        saW[0] *= vs; saW[1] *= vs; saW[2] *= vs;
    }
    __syncthreads();

    // w_eff[b][o][i][t] = aO[o]*aI[i]*aH[t/3]*aW[t%3] * sum_k aK[k]*weight[k,o,i,t]
    const int TOT = CO * CI * 9;
    for (int idx = tid; idx < TOT; idx += 256) {
        int o   = idx / (CI * 9);
        int rem = idx % (CI * 9);
        int i   = rem / 9;
        int t   = rem % 9;
        float ws = 0.f;
        #pragma unroll
        for (int k = 0; k < KK; k++)
            ws = fmaf(saK[k], __ldg(&weight[((k * CO + o) * CI + i) * 9 + t]), ws);
        g_weff[b][o][i][t] = saO[o] * saI[i] * saH[t / 3] * saW[t % 3] * ws;
    }
}

// ---------------------------------------------------------------------------
// Kernel C: per-sample 3x3 conv, pad=1
// block = 32x32 spatial tile x 8 output channels, (32,4)=128 threads
// each thread: 8 y-positions (stride 4) x 8 oc = 64 accumulators
// grid (16 tiles, CO/8, BB)
// ---------------------------------------------------------------------------
#define OCB 8
#define ICB 8

__global__ __launch_bounds__(128) void conv_kernel(const float* __restrict__ x,
                                                   const float* __restrict__ bias,
                                                   float* __restrict__ out) {
    int b    = blockIdx.z;
    int oc0  = blockIdx.y * OCB;
    int tile = blockIdx.x;
    int ty0  = (tile >> 2) * 32;
    int tx0  = (tile & 3) * 32;
    int tx   = threadIdx.x;   // 0..31
    int tyt  = threadIdx.y;   // 0..3
    int tid  = tyt * 32 + tx;

    __shared__ float s_in[ICB][34][34];
    __shared__ float s_wt[ICB][9][OCB];   // oc contiguous -> float4 broadcast loads

    float acc[8][OCB];
    #pragma unroll
    for (int p = 0; p < 8; p++)
        #pragma unroll
        for (int o = 0; o < OCB; o++) acc[p][o] = 0.f;

    const float* xb = x + (size_t)b * CI * HH * WWD;

    for (int ic0 = 0; ic0 < CI; ic0 += ICB) {
        // --- load input tile (34x34 per ic, zero-padded at image borders) ---
        for (int idx = tid; idx < ICB * 34 * 34; idx += 128) {
            int ic = idx / (34 * 34);
            int r  = idx % (34 * 34);
            int yy = r / 34, xx = r % 34;
            int gy = ty0 + yy - 1, gx = tx0 + xx - 1;
            float v = 0.f;
            if (gy >= 0 && gy < HH && gx >= 0 && gx < WWD)
                v = __ldg(&xb[((size_t)(ic0 + ic) * HH + gy) * WWD + gx]);
            s_in[ic][yy][xx] = v;
        }
        // --- load effective weights for this (b, oc block, ic chunk) ---
        for (int idx = tid; idx < ICB * 9 * OCB; idx += 128) {
            int ic = idx / (9 * OCB);
            int r  = idx % (9 * OCB);
            int t  = r / OCB;
            int oc = r % OCB;
            s_wt[ic][t][oc] = g_weff[b][oc0 + oc][ic0 + ic][t];
        }
        __syncthreads();

        #pragma unroll 1
        for (int ic = 0; ic < ICB; ic++) {
            #pragma unroll
            for (int t = 0; t < 9; t++) {
                const int kh = t / 3, kw = t % 3;
                float4 w0 = *(const float4*)(&s_wt[ic][t][0]);
                float4 w1 = *(const float4*)(&s_wt[ic][t][4]);
                #pragma unroll
                for (int py = 0; py < 8; py++) {
                    float v = s_in[ic][tyt + py * 4 + kh][tx + kw];
                    acc[py][0] = fmaf(v, w0.x, acc[py][0]);
                    acc[py][1] = fmaf(v, w0.y, acc[py][1]);
                    acc[py][2] = fmaf(v, w0.z, acc[py][2]);
                    acc[py][3] = fmaf(v, w0.w, acc[py][3]);
                    acc[py][4] = fmaf(v, w1.x, acc[py][4]);
                    acc[py][5] = fmaf(v, w1.y, acc[py][5]);
                    acc[py][6] = fmaf(v, w1.z, acc[py][6]);
                    acc[py][7] = fmaf(v, w1.w, acc[py][7]);
                }
            }
        }
        __syncthreads();
    }

    // --- epilogue: add bias, store ---
    float bv[OCB];
    #pragma unroll
    for (int o = 0; o < OCB; o++) bv[o] = __ldg(&bias[oc0 + o]);

    int xg = tx0 + tx;
    #pragma unroll
    for (int py = 0; py < 8; py++) {
        int yg = ty0 + tyt + py * 4;
        #pragma unroll
        for (int o = 0; o < OCB; o++) {
            out[(((size_t)b * CO + oc0 + o) * HH + yg) * WWD + xg] = acc[py][o] + bv[o];
        }
    }
}

// ---------------------------------------------------------------------------
extern "C" void kernel_launch(void* const* d_in, const int* in_sizes, int n_in,
                              void* d_out, int out_size) {
    const float* x      = (const float*)d_in[0];
    const float* weight = (const float*)d_in[1];
    const float* bias   = (const float*)d_in[2];
    const float* mlp_w  = (const float*)d_in[3];
    const float* mlp_b  = (const float*)d_in[4];
    const float* wK = (const float*)d_in[5];  const float* bK = (const float*)d_in[6];
    const float* wO = (const float*)d_in[7];  const float* bO = (const float*)d_in[8];
    const float* wI = (const float*)d_in[9];  const float* bI = (const float*)d_in[10];
    const float* wH = (const float*)d_in[11]; const float* bH = (const float*)d_in[12];
    const float* wW = (const float*)d_in[13]; const float* bW = (const float*)d_in[14];
    float* out = (float*)d_out;

    gap_kernel<<<dim3(CI, BB), 256>>>(x);
    attn_weff_kernel<<<BB, 256>>>(weight, mlp_w, mlp_b,
                                  wK, bK, wO, bO, wI, bI, wH, bH, wW, bW);
    conv_kernel<<<dim3(16, CO / OCB, BB), dim3(32, 4)>>>(x, bias, out);
}